// round 1
// baseline (speedup 1.0000x reference)
#include <cuda_runtime.h>
#include <cuda_bf16.h>

// Problem constants (fixed shapes: B=64, P=68, H=W=64)
#define HW      4096
#define WDIM    64
#define NTHREADS 256
#define PIX_PER_THREAD 16   // 4096 / 256
#define EPS     1e-5f

__global__ __launch_bounds__(NTHREADS)
void gauss_kl_kernel(const float* __restrict__ hm,
                     const float* __restrict__ means,
                     const float* __restrict__ cov,
                     float* __restrict__ out,
                     float inv_rows)
{
    const int bp  = blockIdx.x;
    const int tid = threadIdx.x;

    // Per-tile Gaussian parameters (broadcast loads, L1/L2 hit)
    const float mx  = means[bp * 2 + 0];
    const float my  = means[bp * 2 + 1];
    const float s00 = cov[bp * 4 + 0];
    const float s01 = cov[bp * 4 + 1];
    const float s10 = cov[bp * 4 + 2];
    const float s11 = cov[bp * 4 + 3];
    const float det = fmaf(s00, s11, -s01 * s10) + EPS;
    const float inv_det = 1.0f / det;
    // lp = -0.5*quad = A*dx^2 + Bq*dx*dy + Cq*dy^2
    const float A  = -0.5f * s11 * inv_det;
    const float Bq =  0.5f * (s01 + s10) * inv_det;
    const float Cq = -0.5f * s00 * inv_det;

    const float4* hm4 = reinterpret_cast<const float4*>(hm + (size_t)bp * HW);

    float4 h[4];
    float  e[PIX_PER_THREAD];
    float  sum = 0.0f;

    // Pass 1: load heatmap (coalesced float4), compute exp(lp), accumulate softmax denom.
#pragma unroll
    for (int k = 0; k < 4; k++) {
        const int i4  = tid + k * NTHREADS;   // float4 index within tile
        h[k] = hm4[i4];
        const int pix = i4 * 4;               // pixel index; 4 consecutive x in same row
        const float y  = (float)(pix >> 6);
        const float x0 = (float)(pix & (WDIM - 1));
        const float dy = y - my;
        const float cdy2 = Cq * dy * dy;
        const float bdy  = Bq * dy;
#pragma unroll
        for (int j = 0; j < 4; j++) {
            const float dx = (x0 + (float)j) - mx;
            const float lp = fmaf(fmaf(A, dx, bdy), dx, cdy2);
            const float ev = __expf(lp);
            e[k * 4 + j] = ev;
            sum += ev;
        }
    }

    // Block reduction of softmax denominator
    __shared__ float ws[NTHREADS / 32];
    __shared__ float s_bcast;
#pragma unroll
    for (int o = 16; o > 0; o >>= 1) sum += __shfl_xor_sync(0xffffffffu, sum, o);
    const int wid = tid >> 5, lid = tid & 31;
    if (lid == 0) ws[wid] = sum;
    __syncthreads();
    if (tid < (NTHREADS / 32)) {
        float v = ws[tid];
#pragma unroll
        for (int o = (NTHREADS / 64); o > 0; o >>= 1)
            v += __shfl_xor_sync(0xffu, v, o);
        if (tid == 0) s_bcast = v;
    }
    __syncthreads();
    const float inv_sum = 1.0f / s_bcast;

    // Pass 2 (registers only): kld = hm * log(hm / (pr + eps)), pr = softmax(lp)
    float kld = 0.0f;
#pragma unroll
    for (int k = 0; k < 4; k++) {
        const float hv[4] = { h[k].x, h[k].y, h[k].z, h[k].w };
#pragma unroll
        for (int j = 0; j < 4; j++) {
            const float pr = fmaf(e[k * 4 + j], inv_sum, EPS);
            const float r  = __fdividef(hv[j], pr);
            kld += hv[j] * __logf(r);
        }
    }

    // Block reduction of KL sum
#pragma unroll
    for (int o = 16; o > 0; o >>= 1) kld += __shfl_xor_sync(0xffffffffu, kld, o);
    if (lid == 0) ws[wid] = kld;
    __syncthreads();
    if (tid < (NTHREADS / 32)) {
        float v = ws[tid];
#pragma unroll
        for (int o = (NTHREADS / 64); o > 0; o >>= 1)
            v += __shfl_xor_sync(0xffu, v, o);
        if (tid == 0) atomicAdd(out, v * inv_rows);
    }
}

extern "C" void kernel_launch(void* const* d_in, const int* in_sizes, int n_in,
                              void* d_out, int out_size)
{
    const float* hm    = (const float*)d_in[0];   // [B,P,H,W]
    const float* means = (const float*)d_in[1];   // [B,P,2]
    const float* cov   = (const float*)d_in[2];   // [B,P,4]
    float* out = (float*)d_out;

    const int n_bp = in_sizes[1] / 2;             // 64*68 = 4352

    cudaMemsetAsync(out, 0, (size_t)out_size * sizeof(float));
    gauss_kl_kernel<<<n_bp, NTHREADS>>>(hm, means, cov, out, 1.0f / (float)n_bp);
}

// round 2
// speedup vs baseline: 1.0981x; 1.0981x over previous
#include <cuda_runtime.h>
#include <cuda_bf16.h>

// Fixed shapes: B=64, P=68, H=W=64  ->  4352 tiles of 4096 pixels
#define HW       4096
#define NTHREADS 256
#define EPS      1e-5f
#define LOG2E    1.4426950408889634f
#define LN2      0.6931471805599453f

__global__ __launch_bounds__(NTHREADS)
void gauss_kl_kernel(const float* __restrict__ hm,
                     const float* __restrict__ means,
                     const float* __restrict__ cov,
                     float* __restrict__ out,
                     float inv_rows)
{
    const int bp  = blockIdx.x;
    const int tid = threadIdx.x;

    // Per-tile Gaussian parameters (broadcast, L2-hit)
    const float mx  = means[bp * 2 + 0];
    const float my  = means[bp * 2 + 1];
    const float s00 = cov[bp * 4 + 0];
    const float s01 = cov[bp * 4 + 1];
    const float s10 = cov[bp * 4 + 2];
    const float s11 = cov[bp * 4 + 3];
    const float det = fmaf(s00, s11, -s01 * s10) + EPS;
    const float inv_det = LOG2E / det;          // fold log2(e) into the quadratic
    // lp2 = log2(exp(-0.5*quad)) = Ac*dx^2 + Bc*dx*dy + Cc*dy^2   (all <= 0)
    const float Ac = -0.5f * s11 * inv_det;
    const float Bc =  0.5f * (s01 + s10) * inv_det;
    const float Cc = -0.5f * s00 * inv_det;

    // Geometry: thread handles 4 groups (k) of 4 consecutive x (same row).
    // i4 = tid + k*256 ; pixel row = tid>>4 + 16k ; x0 = (tid&15)*4 (k-invariant)
    const float x0f = (float)((tid & 15) << 2);
    const float yb  = (float)(tid >> 4);
    const float xm  = x0f - mx;
    const float dx0 = xm,        dx1 = xm + 1.0f;
    const float dx2 = xm + 2.0f, dx3 = xm + 3.0f;
    const float dyb = yb - my;

    // Front-batched streaming loads (no reuse -> bypass-ish, max MLP)
    const float4* hm4 = reinterpret_cast<const float4*>(hm + (size_t)bp * HW);
    float4 h[4];
#pragma unroll
    for (int k = 0; k < 4; k++) h[k] = __ldcs(&hm4[tid + k * NTHREADS]);

    // Pass 1: e = exp2(lp2), S = sum e
    float e[16];
    float S = 0.0f;
#pragma unroll
    for (int k = 0; k < 4; k++) {
        const float dy   = dyb + (float)(16 * k);
        const float bdy  = Bc * dy;
        const float cdy2 = (Cc * dy) * dy;
        const float l0 = fmaf(fmaf(Ac, dx0, bdy), dx0, cdy2);
        const float l1 = fmaf(fmaf(Ac, dx1, bdy), dx1, cdy2);
        const float l2 = fmaf(fmaf(Ac, dx2, bdy), dx2, cdy2);
        const float l3 = fmaf(fmaf(Ac, dx3, bdy), dx3, cdy2);
        const float e0 = exp2f(l0), e1 = exp2f(l1);
        const float e2 = exp2f(l2), e3 = exp2f(l3);
        e[k * 4 + 0] = e0; e[k * 4 + 1] = e1;
        e[k * 4 + 2] = e2; e[k * 4 + 3] = e3;
        S += (e0 + e1) + (e2 + e3);
    }

    // Block reduction of S
    __shared__ float ws[NTHREADS / 32];
    __shared__ float s_bcast;
#pragma unroll
    for (int o = 16; o > 0; o >>= 1) S += __shfl_xor_sync(0xffffffffu, S, o);
    const int wid = tid >> 5, lid = tid & 31;
    if (lid == 0) ws[wid] = S;
    __syncthreads();
    if (tid < (NTHREADS / 32)) {
        float v = ws[tid];
#pragma unroll
        for (int o = (NTHREADS / 64); o > 0; o >>= 1)
            v += __shfl_xor_sync(0xffu, v, o);
        if (tid == 0) s_bcast = v;
    }
    __syncthreads();
    const float Sfull = s_bcast;
    const float c = EPS * Sfull;        // pr + eps = (e + c)/S

    // Pass 2 (registers only):
    //   acc  = sum hm * (lg2(hm) - lg2(e + c))
    //   hsum = sum hm
    float acc = 0.0f, hsum = 0.0f;
#pragma unroll
    for (int k = 0; k < 4; k++) {
        const float hv[4] = { h[k].x, h[k].y, h[k].z, h[k].w };
#pragma unroll
        for (int j = 0; j < 4; j++) {
            const float t  = e[k * 4 + j] + c;
            const float d  = __log2f(hv[j]) - __log2f(t);
            acc  = fmaf(hv[j], d, acc);
            hsum += hv[j];
        }
    }

    // Block reduction of (acc, hsum)
#pragma unroll
    for (int o = 16; o > 0; o >>= 1) {
        acc  += __shfl_xor_sync(0xffffffffu, acc, o);
        hsum += __shfl_xor_sync(0xffffffffu, hsum, o);
    }
    __shared__ float wa[NTHREADS / 32], wh[NTHREADS / 32];
    if (lid == 0) { wa[wid] = acc; wh[wid] = hsum; }
    __syncthreads();
    if (tid < (NTHREADS / 32)) {
        float va = wa[tid], vh = wh[tid];
#pragma unroll
        for (int o = (NTHREADS / 64); o > 0; o >>= 1) {
            va += __shfl_xor_sync(0xffu, va, o);
            vh += __shfl_xor_sync(0xffu, vh, o);
        }
        if (tid == 0) {
            // loss_tile = ln2 * (acc + lg2(S) * hsum)
            const float tile = LN2 * fmaf(__log2f(Sfull), vh, va);
            atomicAdd(out, tile * inv_rows);
        }
    }
}

extern "C" void kernel_launch(void* const* d_in, const int* in_sizes, int n_in,
                              void* d_out, int out_size)
{
    const float* hm    = (const float*)d_in[0];   // [B,P,H,W]
    const float* means = (const float*)d_in[1];   // [B,P,2]
    const float* cov   = (const float*)d_in[2];   // [B,P,4]
    float* out = (float*)d_out;

    const int n_bp = in_sizes[1] / 2;             // 4352

    cudaMemsetAsync(out, 0, (size_t)out_size * sizeof(float));
    gauss_kl_kernel<<<n_bp, NTHREADS>>>(hm, means, cov, out, 1.0f / (float)n_bp);
}